// round 1
// baseline (speedup 1.0000x reference)
#include <cuda_runtime.h>
#include <cstdint>

// Inputs (metadata order):
//   d_in[0] state         float32 [B, A, N, 3]   (B*A*N*3 elems)
//   d_in[1] nodes_coords  float32 [P, 2]
//   d_in[2] adj           float32 [P, N]
//   d_in[3] node_last_visit int32 [B, A]
//   d_in[4] patrol_index  int32   [P]
// Output: float32 [B, A, N, 6]
//
// out[r, n, 0:3] = state[r, n, :]
// out[r, n, 3:5] = nodes_coords[nlv[r], :]
// out[r, n, 5]   = adj[patrol_index[nlv[r]], n]
// where r indexes the flattened (B, A) rows.

__global__ void policy_gather_kernel(const float* __restrict__ state,
                                     const float* __restrict__ coords,
                                     const float* __restrict__ adj,
                                     const int*   __restrict__ nlv,
                                     const int*   __restrict__ pidx,
                                     float* __restrict__ out,
                                     int N) {
    extern __shared__ float s_row[];   // N * 6 floats, laid out like the output row

    const int row = blockIdx.x;
    const int t   = threadIdx.x;

    // Row-constant gathers (L1/L2 resident; broadcast across the block).
    const int   v   = __ldg(nlv + row);
    const int   idx = __ldg(pidx + v);
    const float zx  = __ldg(coords + 2 * v);
    const float zy  = __ldg(coords + 2 * v + 1);

    const float* __restrict__ st = state + (size_t)row * N * 3;
    const float* __restrict__ ar = adj   + (size_t)idx * N;

    // Phase 1: gather into smem tile shaped exactly like the output row.
    for (int n = t; n < N; n += blockDim.x) {
        const float a0 = __ldg(st + 3 * n + 0);
        const float a1 = __ldg(st + 3 * n + 1);
        const float a2 = __ldg(st + 3 * n + 2);
        const float m  = __ldg(ar + n);
        float* d = s_row + 6 * n;
        d[0] = a0;
        d[1] = a1;
        d[2] = a2;
        d[3] = zx;
        d[4] = zy;
        d[5] = m;
    }
    __syncthreads();

    // Phase 2: stream the row out fully coalesced.
    // Row byte offset = row * N * 6 * 4; for N=250 that is 6000B -> 16B aligned.
    float* __restrict__ orow = out + (size_t)row * N * 6;
    const int total = N * 6;
    const int vec4  = total >> 2;          // float4 count

    if ((((uintptr_t)orow) & 0xF) == 0) {
        float4* __restrict__ o4 = reinterpret_cast<float4*>(orow);
        const float4* __restrict__ s4 = reinterpret_cast<const float4*>(s_row);
        for (int j = t; j < vec4; j += blockDim.x) {
            o4[j] = s4[j];
        }
        // scalar tail (none when total % 4 == 0)
        for (int j = (vec4 << 2) + t; j < total; j += blockDim.x) {
            orow[j] = s_row[j];
        }
    } else {
        for (int j = t; j < total; j += blockDim.x) {
            orow[j] = s_row[j];
        }
    }
}

extern "C" void kernel_launch(void* const* d_in, const int* in_sizes, int n_in,
                              void* d_out, int out_size) {
    const float* state  = (const float*)d_in[0];
    const float* coords = (const float*)d_in[1];
    const float* adj    = (const float*)d_in[2];
    const int*   nlv    = (const int*)d_in[3];
    const int*   pidx   = (const int*)d_in[4];
    float*       out    = (float*)d_out;

    const int BA = in_sizes[3];            // B * A rows
    const int P  = in_sizes[4];            // patrol nodes
    const int N  = in_sizes[2] / P;        // graph size (adj is [P, N])

    const int threads = 256;
    const size_t smem = (size_t)N * 6 * sizeof(float);

    policy_gather_kernel<<<BA, threads, smem>>>(state, coords, adj, nlv, pidx, out, N);
}